// round 10
// baseline (speedup 1.0000x reference)
#include <cuda_runtime.h>
#include <cuda_fp16.h>
#include <cstdint>
#include <cstddef>

#define IN_F   1024
#define OUT_F  1024
#define BATCH  4096
#define KB     9216          // B row length (halves): 1024 base + 8192 spline
#define KC     5120          // compressed A row length: 1024 base + 4096 spline
#define BM     128
#define BN     128
#define NITER  80            // 16 dense (64 k each) + 64 sparse (128 orig k each)

__device__ __half  g_A[(size_t)BATCH * KC];    // compressed A (~40 MB)
__device__ __half  g_B[(size_t)OUT_F * KB];    // interleaved B (~19 MB)
__device__ uint8_t g_M[(size_t)BATCH * 1024];  // metadata, 1 byte per (b,i) (~4 MB)

// ---------------------------------------------------------------------------
__device__ __forceinline__ void cpa16(uint32_t d, const void* s) {
    asm volatile("cp.async.cg.shared.global [%0], [%1], 16;" :: "r"(d), "l"(s));
}
__device__ __forceinline__ void ldsm4(uint32_t* r, uint32_t a) {
    asm volatile("ldmatrix.sync.aligned.m8n8.x4.shared.b16 {%0,%1,%2,%3}, [%4];"
                 : "=r"(r[0]), "=r"(r[1]), "=r"(r[2]), "=r"(r[3]) : "r"(a));
}
__device__ __forceinline__ void mma16(float* c, const uint32_t* a, uint32_t b0, uint32_t b1) {
    asm volatile(
        "mma.sync.aligned.m16n8k16.row.col.f32.f16.f16.f32 "
        "{%0,%1,%2,%3},{%4,%5,%6,%7},{%8,%9},{%0,%1,%2,%3};"
        : "+f"(c[0]), "+f"(c[1]), "+f"(c[2]), "+f"(c[3])
        : "r"(a[0]), "r"(a[1]), "r"(a[2]), "r"(a[3]), "r"(b0), "r"(b1));
}
__device__ __forceinline__ void mmasp(float* c, const uint32_t* a,
                                      uint32_t b0, uint32_t b1, uint32_t b2, uint32_t b3,
                                      uint32_t e) {
    asm volatile(
        "mma.sp::ordered_metadata.sync.aligned.m16n8k32.row.col.f32.f16.f16.f32 "
        "{%0,%1,%2,%3},{%4,%5,%6,%7},{%8,%9,%10,%11},{%0,%1,%2,%3},%12,0x0;"
        : "+f"(c[0]), "+f"(c[1]), "+f"(c[2]), "+f"(c[3])
        : "r"(a[0]), "r"(a[1]), "r"(a[2]), "r"(a[3]),
          "r"(b0), "r"(b1), "r"(b2), "r"(b3), "r"(e));
}
__device__ __forceinline__ uint32_t h2u(__half2 h) {
    return *reinterpret_cast<uint32_t*>(&h);
}

// ---------------------------------------------------------------------------
// Prep A: silu + b-spline basis (proven de Boor) -> compressed 2:4 + metadata.
// Interleave slot(j) = j<4 ? 2j : 2(j-4)+1.  Group0 positions map to
// j = {0,4,1,5}; group1 positions map to j = {2,6,3,7}.
// ---------------------------------------------------------------------------
__global__ void build_A(const float* __restrict__ x, const float* __restrict__ grid) {
    int idx = blockIdx.x * blockDim.x + threadIdx.x;

    float xv = x[idx];
    float silu = xv / (1.0f + __expf(-xv));

    float g[12];
#pragma unroll
    for (int j = 0; j < 12; j++) g[j] = __ldg(&grid[j]);   // grid rows identical

    float rk1 = __fdividef(1.0f, g[1] - g[0] + 1e-8f);
    float rk2 = __fdividef(1.0f, g[2] - g[0] + 1e-8f);
    float rk3 = __fdividef(1.0f, g[3] - g[0] + 1e-8f);

    float bb[11];
#pragma unroll
    for (int j = 0; j < 11; j++)
        bb[j] = (xv >= g[j] && xv < g[j + 1]) ? 1.0f : 0.0f;
#pragma unroll
    for (int j = 0; j < 10; j++)
        bb[j] = ((xv - g[j]) * bb[j] + (g[j + 2] - xv) * bb[j + 1]) * rk1;
#pragma unroll
    for (int j = 0; j < 9; j++)
        bb[j] = ((xv - g[j]) * bb[j] + (g[j + 3] - xv) * bb[j + 1]) * rk2;
#pragma unroll
    for (int j = 0; j < 8; j++)
        bb[j] = ((xv - g[j]) * bb[j] + (g[j + 4] - xv) * bb[j + 1]) * rk3;

    // segment index m: g[m] <= x < g[m+1]
    int m = -1;
#pragma unroll
    for (int t = 0; t < 12; t++)
        if (xv >= g[t]) m = t;
    bool inr = (m >= 0 && m <= 10);
    int lo = m - 3, hi = m;

    const int jmap[2][4] = { {0, 4, 1, 5}, {2, 6, 3, 7} };
    float cv[4];
    uint32_t meta = 0;
#pragma unroll
    for (int grp = 0; grp < 2; grp++) {
        int q0 = -1, q1 = -1;
#pragma unroll
        for (int pos = 0; pos < 4; pos++) {
            int j = jmap[grp][pos];
            bool nz = inr && (j >= lo) && (j <= hi);
            if (nz) { if (q0 < 0) q0 = pos; else q1 = pos; }
        }
        if (q0 < 0) { q0 = 0; q1 = 1; }
        else if (q1 < 0) {
            int q = (q0 == 0) ? 1 : 0;
            int a = q0 < q ? q0 : q, b2 = q0 < q ? q : q0;
            q0 = a; q1 = b2;
        }
        cv[grp * 2 + 0] = bb[jmap[grp][q0]];   // zero outside support
        cv[grp * 2 + 1] = bb[jmap[grp][q1]];
        meta |= (uint32_t)(q0 | (q1 << 2)) << (grp * 4);
    }

    int b = idx >> 10;
    int i = idx & 1023;
    size_t arow = (size_t)b * KC;
    g_A[arow + i] = __float2half_rn(silu);

    __half2 p0 = __floats2half2_rn(cv[0], cv[1]);
    __half2 p1 = __floats2half2_rn(cv[2], cv[3]);
    uint2 v = make_uint2(h2u(p0), h2u(p1));
    *reinterpret_cast<uint2*>(&g_A[arow + IN_F + (size_t)i * 4]) = v;

    g_M[(size_t)b * 1024 + i] = (uint8_t)meta;
}

// ---------------------------------------------------------------------------
// Prep B: base weights unchanged; spline weights scaled + column-interleaved.
// ---------------------------------------------------------------------------
__global__ void build_B(const float* __restrict__ bw,
                        const float* __restrict__ sw,
                        const float* __restrict__ sc) {
    int idx = blockIdx.x * blockDim.x + threadIdx.x;
    int o = idx >> 10;
    int i = idx & 1023;

    size_t brow = (size_t)o * KB;
    g_B[brow + i] = __float2half_rn(bw[idx]);

    float s = sc[idx];
    const float* swp = sw + (size_t)idx * 8;
    float v[8];
#pragma unroll
    for (int j = 0; j < 8; j++) v[j] = swp[j] * s;

    // interleaved: slots = (v0, v4, v1, v5, v2, v6, v3, v7)
    __half2 p0 = __floats2half2_rn(v[0], v[4]);
    __half2 p1 = __floats2half2_rn(v[1], v[5]);
    __half2 p2 = __floats2half2_rn(v[2], v[6]);
    __half2 p3 = __floats2half2_rn(v[3], v[7]);
    uint4 pv = make_uint4(h2u(p0), h2u(p1), h2u(p2), h2u(p3));
    *reinterpret_cast<uint4*>(&g_B[brow + IN_F + (size_t)i * 8]) = pv;
}

// ---------------------------------------------------------------------------
// GEMM: dense base (K=1024) + 2:4 sparse spline (orig K=8192, compressed 4096)
// ---------------------------------------------------------------------------
#define ASTG   16384                 // 128 rows * 128 B  (64 compressed halves)
#define BSTG   32768                 // 128 rows * 256 B  (128 orig halves)
#define MSTG   2048                  // 128 rows * 16 B metadata
#define STG    (ASTG + BSTG + MSTG)  // 51200
#define SMEM_TOT (2 * STG)           // 102400

__global__ __launch_bounds__(256, 2) void gemm_sp(float* __restrict__ D) {
    extern __shared__ char smem[];
    const uint32_t sb = (uint32_t)__cvta_generic_to_shared(smem);

    int tid = threadIdx.x, wid = tid >> 5, lane = tid & 31;
    int wm = wid >> 2, wn = wid & 3;          // 2 x 4 warps
    const int m_base = wm * 64;
    const int n_base = wn * 32;

    const int rowA0 = blockIdx.y * BM;
    const __half* Ag = g_A + (size_t)rowA0 * KC;
    const __half* Bg = g_B + (size_t)(blockIdx.x * BN) * KB;
    const uint8_t* Mg = g_M + (size_t)rowA0 * 1024;

    auto load = [&](int it, int s) {
        uint32_t base = sb + s * STG;
        {
            int cA = tid & 7, rA = tid >> 3;
            const __half* src = Ag + it * 64 + cA * 8;
#pragma unroll
            for (int p = 0; p < 4; p++) {
                int row = rA + p * 32;
                cpa16(base + row * 128 + (((cA ^ row) & 7) << 4),
                      src + (size_t)row * KC);
            }
        }
        if (it < 16) {
            int cB = tid & 7, rB = tid >> 3;
            const __half* src = Bg + it * 64 + cB * 8;
#pragma unroll
            for (int p = 0; p < 4; p++) {
                int row = rB + p * 32;
                cpa16(base + ASTG + row * 256 + (((cB ^ row) & 7) << 4),
                      src + (size_t)row * KB);
            }
        } else {
            int cB = tid & 15, rB = tid >> 4;
            const __half* src = Bg + 1024 + (it - 16) * 128 + cB * 8;
#pragma unroll
            for (int p = 0; p < 8; p++) {
                int row = rB + p * 16;
                cpa16(base + ASTG + row * 256 + ((cB & 8) << 4) + ((((cB ^ row)) & 7) << 4),
                      src + (size_t)row * KB);
            }
            if (tid < 128) {
                cpa16(base + ASTG + BSTG + tid * 16,
                      Mg + (size_t)tid * 1024 + (it - 16) * 16);
            }
        }
        asm volatile("cp.async.commit_group;");
    };

    float acc[4][4][4];
#pragma unroll
    for (int m = 0; m < 4; m++)
#pragma unroll
        for (int n = 0; n < 4; n++)
#pragma unroll
            for (int q = 0; q < 4; q++) acc[m][n][q] = 0.0f;

    load(0, 0);

    for (int it = 0; it < NITER; it++) {
        int cur = it & 1;
        if (it + 1 < NITER) {
            load(it + 1, cur ^ 1);
            asm volatile("cp.async.wait_group 1;");
        } else {
            asm volatile("cp.async.wait_group 0;");
        }
        __syncthreads();

        uint32_t sA = sb + cur * STG;
        uint32_t sB = sA + ASTG;
        uint32_t sM = sB + BSTG;

        if (it < 16) {
#pragma unroll
            for (int ks = 0; ks < 4; ks++) {
                int kc = ks * 2 + (lane >> 4);
                uint32_t a[4][4];
#pragma unroll
                for (int mt = 0; mt < 4; mt++) {
                    int row = m_base + mt * 16 + (lane & 15);
                    ldsm4(a[mt], sA + row * 128 + (((kc ^ row) & 7) << 4));
                }
                uint32_t bf[2][4];
#pragma unroll
                for (int np = 0; np < 2; np++) {
                    int row = n_base + np * 16 + ((lane >> 3) & 1) * 8 + (lane & 7);
                    ldsm4(bf[np], sB + row * 256 + (((kc ^ row) & 7) << 4));
                }
#pragma unroll
                for (int mt = 0; mt < 4; mt++)
#pragma unroll
                    for (int nt = 0; nt < 4; nt++)
                        mma16(acc[mt][nt], a[mt],
                              bf[nt >> 1][nt & 1], bf[nt >> 1][2 + (nt & 1)]);
            }
        } else {
#pragma unroll
            for (int s = 0; s < 4; s++) {
                uint32_t a[4][4];
                uint32_t em[4];
#pragma unroll
                for (int mt = 0; mt < 4; mt++) {
                    int row = m_base + mt * 16 + (lane & 15);
                    int kc = s * 2 + (lane >> 4);
                    ldsm4(a[mt], sA + row * 128 + (((kc ^ row) & 7) << 4));
                    // k-split metadata layout:
                    //   T(lane%4==0): [row i, k0-15] | [row i+8, k0-15] << 16
                    //   T(lane%4==1): [row i, k16-31] | [row i+8, k16-31] << 16
                    int rlow = m_base + mt * 16 + (lane >> 2);
                    uint32_t off = sM + rlow * 16 + s * 4 + ((lane & 1) << 1);
                    uint32_t lo16, hi16;
                    asm volatile("ld.shared.u16 %0, [%1];" : "=r"(lo16) : "r"(off));
                    asm volatile("ld.shared.u16 %0, [%1];" : "=r"(hi16) : "r"(off + 128));
                    em[mt] = lo16 | (hi16 << 16);
                }
                uint32_t fb[2][8];
#pragma unroll
                for (int np = 0; np < 2; np++) {
                    int row = n_base + np * 16 + ((lane >> 3) & 1) * 8 + (lane & 7);
                    int c1 = s * 4 + (lane >> 4);
                    int c2 = c1 + 2;
                    ldsm4(&fb[np][0], sB + row * 256 + ((c1 & 8) << 4) + (((c1 ^ row) & 7) << 4));
                    ldsm4(&fb[np][4], sB + row * 256 + ((c2 & 8) << 4) + (((c2 ^ row) & 7) << 4));
                }
#pragma unroll
                for (int mt = 0; mt < 4; mt++)
#pragma unroll
                    for (int nt = 0; nt < 4; nt++) {
                        int np = nt >> 1, sub = nt & 1;
                        mmasp(acc[mt][nt], a[mt],
                              fb[np][sub], fb[np][2 + sub], fb[np][4 + sub], fb[np][6 + sub],
                              em[mt]);
                    }
            }
        }
        __syncthreads();
    }

    // Epilogue
    float* Dp = D + (size_t)(rowA0 + m_base) * OUT_F + blockIdx.x * BN + n_base;
#pragma unroll
    for (int mt = 0; mt < 4; mt++) {
#pragma unroll
        for (int nt = 0; nt < 4; nt++) {
            int r  = mt * 16 + (lane >> 2);
            int cc = nt * 8 + (lane & 3) * 2;
            *reinterpret_cast<float2*>(&Dp[(size_t)r * OUT_F + cc]) =
                make_float2(acc[mt][nt][0], acc[mt][nt][1]);
            *reinterpret_cast<float2*>(&Dp[(size_t)(r + 8) * OUT_F + cc]) =
                make_float2(acc[mt][nt][2], acc[mt][nt][3]);
        }
    }
}

// ---------------------------------------------------------------------------
extern "C" void kernel_launch(void* const* d_in, const int* in_sizes, int n_in,
                              void* d_out, int out_size) {
    const float* x    = (const float*)d_in[0];
    const float* bw   = (const float*)d_in[1];
    const float* sw   = (const float*)d_in[2];
    const float* sc   = (const float*)d_in[3];
    const float* grid = (const float*)d_in[4];
    float* out = (float*)d_out;

    build_A<<<(BATCH * IN_F) / 256, 256>>>(x, grid);
    build_B<<<(OUT_F * IN_F) / 256, 256>>>(bw, sw, sc);

    cudaFuncSetAttribute(gemm_sp, cudaFuncAttributeMaxDynamicSharedMemorySize, SMEM_TOT);
    dim3 grd(OUT_F / BN, BATCH / BM);   // (8, 32) = 256 CTAs, 2 per SM
    gemm_sp<<<grd, 256, SMEM_TOT>>>(out);
}

// round 11
// speedup vs baseline: 1.1785x; 1.1785x over previous
#include <cuda_runtime.h>
#include <cuda_fp16.h>
#include <cstdint>
#include <cstddef>

#define IN_F   1024
#define OUT_F  1024
#define BATCH  4096
#define KB     9216          // B row length (halves): 1024 base + 8192 spline
#define KC     5120          // compressed A row length: 1024 base + 4096 spline
#define BM     128
#define BN     128
#define NITER  80            // 16 dense + 64 sparse iters

__device__ __half  g_A[(size_t)BATCH * KC];    // compressed A (~40 MB)
__device__ __half  g_B[(size_t)OUT_F * KB];    // interleaved B (~19 MB)
// Swizzled metadata: [B rowblock R(256)][rlo(8)][feature-pair f(512)] u32 words;
// word = meta16(row R*16+rlo, f) | meta16(row R*16+rlo+8, f) << 16
__device__ uint8_t g_M[(size_t)BATCH * 1024];  // 4 MB

// ---------------------------------------------------------------------------
__device__ __forceinline__ void cpa16(uint32_t d, const void* s) {
    asm volatile("cp.async.cg.shared.global [%0], [%1], 16;" :: "r"(d), "l"(s));
}
__device__ __forceinline__ void ldsm4(uint32_t* r, uint32_t a) {
    asm volatile("ldmatrix.sync.aligned.m8n8.x4.shared.b16 {%0,%1,%2,%3}, [%4];"
                 : "=r"(r[0]), "=r"(r[1]), "=r"(r[2]), "=r"(r[3]) : "r"(a));
}
__device__ __forceinline__ void mma16(float* c, const uint32_t* a, uint32_t b0, uint32_t b1) {
    asm volatile(
        "mma.sync.aligned.m16n8k16.row.col.f32.f16.f16.f32 "
        "{%0,%1,%2,%3},{%4,%5,%6,%7},{%8,%9},{%0,%1,%2,%3};"
        : "+f"(c[0]), "+f"(c[1]), "+f"(c[2]), "+f"(c[3])
        : "r"(a[0]), "r"(a[1]), "r"(a[2]), "r"(a[3]), "r"(b0), "r"(b1));
}
__device__ __forceinline__ void mmasp(float* c, const uint32_t* a,
                                      uint32_t b0, uint32_t b1, uint32_t b2, uint32_t b3,
                                      uint32_t e) {
    asm volatile(
        "mma.sp::ordered_metadata.sync.aligned.m16n8k32.row.col.f32.f16.f16.f32 "
        "{%0,%1,%2,%3},{%4,%5,%6,%7},{%8,%9,%10,%11},{%0,%1,%2,%3},%12,0x0;"
        : "+f"(c[0]), "+f"(c[1]), "+f"(c[2]), "+f"(c[3])
        : "r"(a[0]), "r"(a[1]), "r"(a[2]), "r"(a[3]),
          "r"(b0), "r"(b1), "r"(b2), "r"(b3), "r"(e));
}
__device__ __forceinline__ uint32_t h2u(__half2 h) {
    return *reinterpret_cast<uint32_t*>(&h);
}

// ---------------------------------------------------------------------------
// Prep A: de Boor basis + table-driven 2:4 compression.
// Interleave slot(j) = j<4 ? 2j : 2(j-4)+1; group0 = {j0,j4,j1,j5}, group1 = {j2,j6,j3,j7}.
// Metadata byte and value-slot assignment are pure functions of segment m.
// ---------------------------------------------------------------------------
__global__ void build_A(const float* __restrict__ x, const float* __restrict__ grid) {
    int idx = blockIdx.x * blockDim.x + threadIdx.x;

    float xv = x[idx];
    float silu = xv / (1.0f + __expf(-xv));

    float g[12];
#pragma unroll
    for (int j = 0; j < 12; j++) g[j] = __ldg(&grid[j]);   // grid rows identical

    float rk1 = __fdividef(1.0f, g[1] - g[0] + 1e-8f);
    float rk2 = __fdividef(1.0f, g[2] - g[0] + 1e-8f);
    float rk3 = __fdividef(1.0f, g[3] - g[0] + 1e-8f);

    float bb[11];
#pragma unroll
    for (int j = 0; j < 11; j++)
        bb[j] = (xv >= g[j] && xv < g[j + 1]) ? 1.0f : 0.0f;
#pragma unroll
    for (int j = 0; j < 10; j++)
        bb[j] = ((xv - g[j]) * bb[j] + (g[j + 2] - xv) * bb[j + 1]) * rk1;
#pragma unroll
    for (int j = 0; j < 9; j++)
        bb[j] = ((xv - g[j]) * bb[j] + (g[j + 3] - xv) * bb[j + 1]) * rk2;
#pragma unroll
    for (int j = 0; j < 8; j++)
        bb[j] = ((xv - g[j]) * bb[j] + (g[j + 4] - xv) * bb[j + 1]) * rk3;

    // segment index: g[m] <= x < g[m+1]
    int m = -1;
#pragma unroll
    for (int t = 0; t < 12; t++)
        if (xv >= g[t]) m = t;

    // Compressed values: selects verified per-m against the position table.
    // Any slot not in the support window selects a bb that is exactly 0 there.
    float cv0 = (m >= 4 && m <= 7) ? bb[4] : bb[0];
    float cv1 = (m <= 4) ? bb[1] : bb[5];
    float cv2 = (m <= 5) ? bb[2] : bb[6];
    float cv3 = (m <= 6) ? bb[3] : bb[7];

    // Metadata LUT (nibble = q0 | q1<<2 per 4-group, byte = g0 | g1<<4), m=0..10
    const unsigned long long MLO = 0xDD9D8D8988484844ULL;   // m = 0..7
    const unsigned long long MHI = 0x4444444444C4D4DCULL;   // m = 8..10 (rest 0x44)
    unsigned um = (unsigned)m;
    uint32_t meta;
    if (um < 8)        meta = (uint32_t)(MLO >> (um * 8)) & 0xFF;
    else if (um <= 10) meta = (uint32_t)(MHI >> ((um - 8) * 8)) & 0xFF;
    else               meta = 0x44;

    int b = idx >> 10;
    int i = idx & 1023;
    size_t arow = (size_t)b * KC;
    g_A[arow + i] = __float2half_rn(silu);

    __half2 p0 = __floats2half2_rn(cv0, cv1);
    __half2 p1 = __floats2half2_rn(cv2, cv3);
    uint2 v = make_uint2(h2u(p0), h2u(p1));
    __stcs(reinterpret_cast<uint2*>(&g_A[arow + IN_F + (size_t)i * 4]), v);

    // Swizzled metadata write: word(R=b>>4, rlo=b&7, f=i>>1),
    // low/high 16 selected by (b>>3)&1, byte within u16 by i&1.
    size_t maddr = (size_t)(b >> 4) * 16384 + (size_t)(b & 7) * 2048
                 + (size_t)(i >> 1) * 4 + ((b >> 3) & 1) * 2 + (i & 1);
    g_M[maddr] = (uint8_t)meta;
}

// ---------------------------------------------------------------------------
// Prep B: base weights unchanged; spline weights scaled + column-interleaved.
// ---------------------------------------------------------------------------
__global__ void build_B(const float* __restrict__ bw,
                        const float* __restrict__ sw,
                        const float* __restrict__ sc) {
    int idx = blockIdx.x * blockDim.x + threadIdx.x;
    int o = idx >> 10;
    int i = idx & 1023;

    size_t brow = (size_t)o * KB;
    g_B[brow + i] = __float2half_rn(bw[idx]);

    float s = sc[idx];
    const float* swp = sw + (size_t)idx * 8;
    float v[8];
#pragma unroll
    for (int j = 0; j < 8; j++) v[j] = swp[j] * s;

    __half2 p0 = __floats2half2_rn(v[0], v[4]);
    __half2 p1 = __floats2half2_rn(v[1], v[5]);
    __half2 p2 = __floats2half2_rn(v[2], v[6]);
    __half2 p3 = __floats2half2_rn(v[3], v[7]);
    uint4 pv = make_uint4(h2u(p0), h2u(p1), h2u(p2), h2u(p3));
    *reinterpret_cast<uint4*>(&g_B[brow + IN_F + (size_t)i * 8]) = pv;
}

// ---------------------------------------------------------------------------
// GEMM: dense base (K=1024) + 2:4 sparse spline (orig K=8192)
// ---------------------------------------------------------------------------
#define ASTG   16384                 // 128 rows * 128 B
#define BSTG   32768                 // 128 rows * 256 B
#define MSTG   2048                  // 8 R * 8 rlo * 8 f * 4 B
#define STG    (ASTG + BSTG + MSTG)  // 51200
#define SMEM_TOT (2 * STG)           // 102400

__global__ __launch_bounds__(256, 2) void gemm_sp(float* __restrict__ D) {
    extern __shared__ char smem[];
    const uint32_t sb = (uint32_t)__cvta_generic_to_shared(smem);

    int tid = threadIdx.x, wid = tid >> 5, lane = tid & 31;
    int wm = wid >> 2, wn = wid & 3;          // 2 x 4 warps
    const int m_base = wm * 64;
    const int n_base = wn * 32;

    const int rowA0 = blockIdx.y * BM;
    const __half* Ag = g_A + (size_t)rowA0 * KC;
    const __half* Bg = g_B + (size_t)(blockIdx.x * BN) * KB;
    const uint8_t* Mg = g_M + (size_t)(rowA0 >> 4) * 16384;

    auto load = [&](int it, int s) {
        uint32_t base = sb + s * STG;
        {
            int cA = tid & 7, rA = tid >> 3;
            const __half* src = Ag + it * 64 + cA * 8;
#pragma unroll
            for (int p = 0; p < 4; p++) {
                int row = rA + p * 32;
                cpa16(base + row * 128 + (((cA ^ row) & 7) << 4),
                      src + (size_t)row * KC);
            }
        }
        if (it < 16) {
            int cB = tid & 7, rB = tid >> 3;
            const __half* src = Bg + it * 64 + cB * 8;
#pragma unroll
            for (int p = 0; p < 4; p++) {
                int row = rB + p * 32;
                cpa16(base + ASTG + row * 256 + (((cB ^ row) & 7) << 4),
                      src + (size_t)row * KB);
            }
        } else {
            int cB = tid & 15, rB = tid >> 4;
            const __half* src = Bg + 1024 + (it - 16) * 128 + cB * 8;
#pragma unroll
            for (int p = 0; p < 8; p++) {
                int row = rB + p * 16;
                cpa16(base + ASTG + row * 256 + ((cB & 8) << 4) + ((((cB ^ row)) & 7) << 4),
                      src + (size_t)row * KB);
            }
            // swizzled metadata: 64 chunks of 32 B ([R][rlo] pairs), 2 x 16 B each
            if (tid < 128) {
                int chunk = tid >> 1, half16 = tid & 1;
                int R = chunk >> 3, rlo = chunk & 7;
                cpa16(base + ASTG + BSTG + chunk * 32 + half16 * 16,
                      Mg + ((size_t)R * 8 + rlo) * 2048 + (it - 16) * 32 + half16 * 16);
            }
        }
        asm volatile("cp.async.commit_group;");
    };

    float acc[4][4][4];
#pragma unroll
    for (int m = 0; m < 4; m++)
#pragma unroll
        for (int n = 0; n < 4; n++)
#pragma unroll
            for (int q = 0; q < 4; q++) acc[m][n][q] = 0.0f;

    load(0, 0);

    for (int it = 0; it < NITER; it++) {
        int cur = it & 1;
        if (it + 1 < NITER) {
            load(it + 1, cur ^ 1);
            asm volatile("cp.async.wait_group 1;");
        } else {
            asm volatile("cp.async.wait_group 0;");
        }
        __syncthreads();

        uint32_t sA = sb + cur * STG;
        uint32_t sB = sA + ASTG;
        uint32_t sM = sB + BSTG;

        if (it < 16) {
#pragma unroll
            for (int ks = 0; ks < 4; ks++) {
                int kc = ks * 2 + (lane >> 4);
                uint32_t a[4][4];
#pragma unroll
                for (int mt = 0; mt < 4; mt++) {
                    int row = m_base + mt * 16 + (lane & 15);
                    ldsm4(a[mt], sA + row * 128 + (((kc ^ row) & 7) << 4));
                }
                uint32_t bf[2][4];
#pragma unroll
                for (int np = 0; np < 2; np++) {
                    int row = n_base + np * 16 + ((lane >> 3) & 1) * 8 + (lane & 7);
                    ldsm4(bf[np], sB + row * 256 + (((kc ^ row) & 7) << 4));
                }
#pragma unroll
                for (int mt = 0; mt < 4; mt++)
#pragma unroll
                    for (int nt = 0; nt < 4; nt++)
                        mma16(acc[mt][nt], a[mt],
                              bf[nt >> 1][nt & 1], bf[nt >> 1][2 + (nt & 1)]);
            }
        } else {
#pragma unroll
            for (int s = 0; s < 4; s++) {
                uint32_t a[4][4];
                uint32_t em[4];
#pragma unroll
                for (int mt = 0; mt < 4; mt++) {
                    int row = m_base + mt * 16 + (lane & 15);
                    int kc = s * 2 + (lane >> 4);
                    ldsm4(a[mt], sA + row * 128 + (((kc ^ row) & 7) << 4));
                    // one 32-bit word per (mt, s): already k-split packed
                    int R_local = (m_base >> 4) + mt;
                    uint32_t eaddr = sM +
                        (uint32_t)(((R_local * 8 + (lane >> 2)) * 8 + s * 2 + (lane & 1)) * 4);
                    asm volatile("ld.shared.b32 %0, [%1];" : "=r"(em[mt]) : "r"(eaddr));
                }
                uint32_t fb[2][8];
#pragma unroll
                for (int np = 0; np < 2; np++) {
                    int row = n_base + np * 16 + ((lane >> 3) & 1) * 8 + (lane & 7);
                    int c1 = s * 4 + (lane >> 4);
                    int c2 = c1 + 2;
                    ldsm4(&fb[np][0], sB + row * 256 + ((c1 & 8) << 4) + (((c1 ^ row) & 7) << 4));
                    ldsm4(&fb[np][4], sB + row * 256 + ((c2 & 8) << 4) + (((c2 ^ row) & 7) << 4));
                }
#pragma unroll
                for (int mt = 0; mt < 4; mt++)
#pragma unroll
                    for (int nt = 0; nt < 4; nt++) {
                        int np = nt >> 1, sub = nt & 1;
                        mmasp(acc[mt][nt], a[mt],
                              fb[np][sub], fb[np][2 + sub], fb[np][4 + sub], fb[np][6 + sub],
                              em[mt]);
                    }
            }
        }
        __syncthreads();
    }

    // Epilogue
    float* Dp = D + (size_t)(rowA0 + m_base) * OUT_F + blockIdx.x * BN + n_base;
#pragma unroll
    for (int mt = 0; mt < 4; mt++) {
#pragma unroll
        for (int nt = 0; nt < 4; nt++) {
            int r  = mt * 16 + (lane >> 2);
            int cc = nt * 8 + (lane & 3) * 2;
            *reinterpret_cast<float2*>(&Dp[(size_t)r * OUT_F + cc]) =
                make_float2(acc[mt][nt][0], acc[mt][nt][1]);
            *reinterpret_cast<float2*>(&Dp[(size_t)(r + 8) * OUT_F + cc]) =
                make_float2(acc[mt][nt][2], acc[mt][nt][3]);
        }
    }
}

// ---------------------------------------------------------------------------
extern "C" void kernel_launch(void* const* d_in, const int* in_sizes, int n_in,
                              void* d_out, int out_size) {
    const float* x    = (const float*)d_in[0];
    const float* bw   = (const float*)d_in[1];
    const float* sw   = (const float*)d_in[2];
    const float* sc   = (const float*)d_in[3];
    const float* grid = (const float*)d_in[4];
    float* out = (float*)d_out;

    build_A<<<(BATCH * IN_F) / 256, 256>>>(x, grid);
    build_B<<<(OUT_F * IN_F) / 256, 256>>>(bw, sw, sc);

    cudaFuncSetAttribute(gemm_sp, cudaFuncAttributeMaxDynamicSharedMemorySize, SMEM_TOT);
    dim3 grd(OUT_F / BN, BATCH / BM);   // (8, 32) = 256 CTAs, 2 per SM
    gemm_sp<<<grd, 256, SMEM_TOT>>>(out);
}

// round 12
// speedup vs baseline: 1.1794x; 1.0008x over previous
#include <cuda_runtime.h>
#include <cuda_fp16.h>
#include <cstdint>
#include <cstddef>

#define IN_F   1024
#define OUT_F  1024
#define BATCH  4096
#define KB     9216          // B row length (halves): 1024 base + 8192 spline
#define KC     5120          // compressed A row length: 1024 base + 4096 spline
#define BM     128
#define BN     128
#define NITER  80            // 16 dense + 64 sparse iters

__device__ __half  g_A[(size_t)BATCH * KC];    // compressed A (~40 MB)
__device__ __half  g_B[(size_t)OUT_F * KB];    // interleaved B (~19 MB)
// Swizzled metadata: [B rowblock R(256)][rlo(8)][feature-pair f(512)] u32 words;
// word = meta16(row R*16+rlo, f) | meta16(row R*16+rlo+8, f) << 16
__device__ uint8_t g_M[(size_t)BATCH * 1024];  // 4 MB

// ---------------------------------------------------------------------------
__device__ __forceinline__ void cpa16(uint32_t d, const void* s) {
    asm volatile("cp.async.cg.shared.global [%0], [%1], 16;" :: "r"(d), "l"(s));
}
__device__ __forceinline__ void ldsm4(uint32_t* r, uint32_t a) {
    asm volatile("ldmatrix.sync.aligned.m8n8.x4.shared.b16 {%0,%1,%2,%3}, [%4];"
                 : "=r"(r[0]), "=r"(r[1]), "=r"(r[2]), "=r"(r[3]) : "r"(a));
}
__device__ __forceinline__ void mma16(float* c, const uint32_t* a, uint32_t b0, uint32_t b1) {
    asm volatile(
        "mma.sync.aligned.m16n8k16.row.col.f32.f16.f16.f32 "
        "{%0,%1,%2,%3},{%4,%5,%6,%7},{%8,%9},{%0,%1,%2,%3};"
        : "+f"(c[0]), "+f"(c[1]), "+f"(c[2]), "+f"(c[3])
        : "r"(a[0]), "r"(a[1]), "r"(a[2]), "r"(a[3]), "r"(b0), "r"(b1));
}
__device__ __forceinline__ void mmasp(float* c, const uint32_t* a,
                                      uint32_t b0, uint32_t b1, uint32_t b2, uint32_t b3,
                                      uint32_t e) {
    asm volatile(
        "mma.sp::ordered_metadata.sync.aligned.m16n8k32.row.col.f32.f16.f16.f32 "
        "{%0,%1,%2,%3},{%4,%5,%6,%7},{%8,%9,%10,%11},{%0,%1,%2,%3},%12,0x0;"
        : "+f"(c[0]), "+f"(c[1]), "+f"(c[2]), "+f"(c[3])
        : "r"(a[0]), "r"(a[1]), "r"(a[2]), "r"(a[3]),
          "r"(b0), "r"(b1), "r"(b2), "r"(b3), "r"(e));
}
__device__ __forceinline__ uint32_t h2u(__half2 h) {
    return *reinterpret_cast<uint32_t*>(&h);
}

// ---------------------------------------------------------------------------
// Prep A: de Boor basis + table-driven 2:4 compression.
// Interleave slot(j) = j<4 ? 2j : 2(j-4)+1; group0 = {j0,j4,j1,j5}, group1 = {j2,j6,j3,j7}.
// Metadata byte and value-slot assignment are pure functions of segment m.
// ---------------------------------------------------------------------------
__global__ void build_A(const float* __restrict__ x, const float* __restrict__ grid) {
    int idx = blockIdx.x * blockDim.x + threadIdx.x;

    float xv = x[idx];
    float silu = xv / (1.0f + __expf(-xv));

    float g[12];
#pragma unroll
    for (int j = 0; j < 12; j++) g[j] = __ldg(&grid[j]);   // grid rows identical

    float rk1 = __fdividef(1.0f, g[1] - g[0] + 1e-8f);
    float rk2 = __fdividef(1.0f, g[2] - g[0] + 1e-8f);
    float rk3 = __fdividef(1.0f, g[3] - g[0] + 1e-8f);

    float bb[11];
#pragma unroll
    for (int j = 0; j < 11; j++)
        bb[j] = (xv >= g[j] && xv < g[j + 1]) ? 1.0f : 0.0f;
#pragma unroll
    for (int j = 0; j < 10; j++)
        bb[j] = ((xv - g[j]) * bb[j] + (g[j + 2] - xv) * bb[j + 1]) * rk1;
#pragma unroll
    for (int j = 0; j < 9; j++)
        bb[j] = ((xv - g[j]) * bb[j] + (g[j + 3] - xv) * bb[j + 1]) * rk2;
#pragma unroll
    for (int j = 0; j < 8; j++)
        bb[j] = ((xv - g[j]) * bb[j] + (g[j + 4] - xv) * bb[j + 1]) * rk3;

    // segment index: g[m] <= x < g[m+1]
    int m = -1;
#pragma unroll
    for (int t = 0; t < 12; t++)
        if (xv >= g[t]) m = t;

    // Compressed values: selects verified per-m against the position table.
    // Any slot not in the support window selects a bb that is exactly 0 there.
    float cv0 = (m >= 4 && m <= 7) ? bb[4] : bb[0];
    float cv1 = (m <= 4) ? bb[1] : bb[5];
    float cv2 = (m <= 5) ? bb[2] : bb[6];
    float cv3 = (m <= 6) ? bb[3] : bb[7];

    // Metadata LUT (nibble = q0 | q1<<2 per 4-group, byte = g0 | g1<<4), m=0..10
    const unsigned long long MLO = 0xDD9D8D8988484844ULL;   // m = 0..7
    const unsigned long long MHI = 0x4444444444C4D4DCULL;   // m = 8..10 (rest 0x44)
    unsigned um = (unsigned)m;
    uint32_t meta;
    if (um < 8)        meta = (uint32_t)(MLO >> (um * 8)) & 0xFF;
    else if (um <= 10) meta = (uint32_t)(MHI >> ((um - 8) * 8)) & 0xFF;
    else               meta = 0x44;

    int b = idx >> 10;
    int i = idx & 1023;
    size_t arow = (size_t)b * KC;
    g_A[arow + i] = __float2half_rn(silu);

    __half2 p0 = __floats2half2_rn(cv0, cv1);
    __half2 p1 = __floats2half2_rn(cv2, cv3);
    uint2 v = make_uint2(h2u(p0), h2u(p1));
    __stcs(reinterpret_cast<uint2*>(&g_A[arow + IN_F + (size_t)i * 4]), v);

    // Swizzled metadata write: word(R=b>>4, rlo=b&7, f=i>>1),
    // low/high 16 selected by (b>>3)&1, byte within u16 by i&1.
    size_t maddr = (size_t)(b >> 4) * 16384 + (size_t)(b & 7) * 2048
                 + (size_t)(i >> 1) * 4 + ((b >> 3) & 1) * 2 + (i & 1);
    g_M[maddr] = (uint8_t)meta;
}

// ---------------------------------------------------------------------------
// Prep B: base weights unchanged; spline weights scaled + column-interleaved.
// ---------------------------------------------------------------------------
__global__ void build_B(const float* __restrict__ bw,
                        const float* __restrict__ sw,
                        const float* __restrict__ sc) {
    int idx = blockIdx.x * blockDim.x + threadIdx.x;
    int o = idx >> 10;
    int i = idx & 1023;

    size_t brow = (size_t)o * KB;
    g_B[brow + i] = __float2half_rn(bw[idx]);

    float s = sc[idx];
    const float* swp = sw + (size_t)idx * 8;
    float v[8];
#pragma unroll
    for (int j = 0; j < 8; j++) v[j] = swp[j] * s;

    __half2 p0 = __floats2half2_rn(v[0], v[4]);
    __half2 p1 = __floats2half2_rn(v[1], v[5]);
    __half2 p2 = __floats2half2_rn(v[2], v[6]);
    __half2 p3 = __floats2half2_rn(v[3], v[7]);
    uint4 pv = make_uint4(h2u(p0), h2u(p1), h2u(p2), h2u(p3));
    *reinterpret_cast<uint4*>(&g_B[brow + IN_F + (size_t)i * 8]) = pv;
}

// ---------------------------------------------------------------------------
// GEMM: dense base (K=1024) + 2:4 sparse spline (orig K=8192)
// ---------------------------------------------------------------------------
#define ASTG   16384                 // 128 rows * 128 B
#define BSTG   32768                 // 128 rows * 256 B
#define MSTG   2048                  // 8 R * 8 rlo * 8 f * 4 B
#define STG    (ASTG + BSTG + MSTG)  // 51200
#define SMEM_TOT (2 * STG)           // 102400

__global__ __launch_bounds__(256, 2) void gemm_sp(float* __restrict__ D) {
    extern __shared__ char smem[];
    const uint32_t sb = (uint32_t)__cvta_generic_to_shared(smem);

    int tid = threadIdx.x, wid = tid >> 5, lane = tid & 31;
    int wm = wid >> 2, wn = wid & 3;          // 2 x 4 warps
    const int m_base = wm * 64;
    const int n_base = wn * 32;

    const int rowA0 = blockIdx.y * BM;
    const __half* Ag = g_A + (size_t)rowA0 * KC;
    const __half* Bg = g_B + (size_t)(blockIdx.x * BN) * KB;
    const uint8_t* Mg = g_M + (size_t)(rowA0 >> 4) * 16384;

    auto load = [&](int it, int s) {
        uint32_t base = sb + s * STG;
        {
            int cA = tid & 7, rA = tid >> 3;
            const __half* src = Ag + it * 64 + cA * 8;
#pragma unroll
            for (int p = 0; p < 4; p++) {
                int row = rA + p * 32;
                cpa16(base + row * 128 + (((cA ^ row) & 7) << 4),
                      src + (size_t)row * KC);
            }
        }
        if (it < 16) {
            int cB = tid & 7, rB = tid >> 3;
            const __half* src = Bg + it * 64 + cB * 8;
#pragma unroll
            for (int p = 0; p < 4; p++) {
                int row = rB + p * 32;
                cpa16(base + ASTG + row * 256 + (((cB ^ row) & 7) << 4),
                      src + (size_t)row * KB);
            }
        } else {
            int cB = tid & 15, rB = tid >> 4;
            const __half* src = Bg + 1024 + (it - 16) * 128 + cB * 8;
#pragma unroll
            for (int p = 0; p < 8; p++) {
                int row = rB + p * 16;
                cpa16(base + ASTG + row * 256 + ((cB & 8) << 4) + ((((cB ^ row)) & 7) << 4),
                      src + (size_t)row * KB);
            }
            // swizzled metadata: 64 chunks of 32 B ([R][rlo] pairs), 2 x 16 B each
            if (tid < 128) {
                int chunk = tid >> 1, half16 = tid & 1;
                int R = chunk >> 3, rlo = chunk & 7;
                cpa16(base + ASTG + BSTG + chunk * 32 + half16 * 16,
                      Mg + ((size_t)R * 8 + rlo) * 2048 + (it - 16) * 32 + half16 * 16);
            }
        }
        asm volatile("cp.async.commit_group;");
    };

    float acc[4][4][4];
#pragma unroll
    for (int m = 0; m < 4; m++)
#pragma unroll
        for (int n = 0; n < 4; n++)
#pragma unroll
            for (int q = 0; q < 4; q++) acc[m][n][q] = 0.0f;

    load(0, 0);

    for (int it = 0; it < NITER; it++) {
        int cur = it & 1;
        if (it + 1 < NITER) {
            load(it + 1, cur ^ 1);
            asm volatile("cp.async.wait_group 1;");
        } else {
            asm volatile("cp.async.wait_group 0;");
        }
        __syncthreads();

        uint32_t sA = sb + cur * STG;
        uint32_t sB = sA + ASTG;
        uint32_t sM = sB + BSTG;

        if (it < 16) {
#pragma unroll
            for (int ks = 0; ks < 4; ks++) {
                int kc = ks * 2 + (lane >> 4);
                uint32_t a[4][4];
#pragma unroll
                for (int mt = 0; mt < 4; mt++) {
                    int row = m_base + mt * 16 + (lane & 15);
                    ldsm4(a[mt], sA + row * 128 + (((kc ^ row) & 7) << 4));
                }
                uint32_t bf[2][4];
#pragma unroll
                for (int np = 0; np < 2; np++) {
                    int row = n_base + np * 16 + ((lane >> 3) & 1) * 8 + (lane & 7);
                    ldsm4(bf[np], sB + row * 256 + (((kc ^ row) & 7) << 4));
                }
#pragma unroll
                for (int mt = 0; mt < 4; mt++)
#pragma unroll
                    for (int nt = 0; nt < 4; nt++)
                        mma16(acc[mt][nt], a[mt],
                              bf[nt >> 1][nt & 1], bf[nt >> 1][2 + (nt & 1)]);
            }
        } else {
#pragma unroll
            for (int s = 0; s < 4; s++) {
                uint32_t a[4][4];
                uint32_t em[4];
#pragma unroll
                for (int mt = 0; mt < 4; mt++) {
                    int row = m_base + mt * 16 + (lane & 15);
                    int kc = s * 2 + (lane >> 4);
                    ldsm4(a[mt], sA + row * 128 + (((kc ^ row) & 7) << 4));
                    // one 32-bit word per (mt, s): already k-split packed
                    int R_local = (m_base >> 4) + mt;
                    uint32_t eaddr = sM +
                        (uint32_t)(((R_local * 8 + (lane >> 2)) * 8 + s * 2 + (lane & 1)) * 4);
                    asm volatile("ld.shared.b32 %0, [%1];" : "=r"(em[mt]) : "r"(eaddr));
                }
                uint32_t fb[2][8];
#pragma unroll
                for (int np = 0; np < 2; np++) {
                    int row = n_base + np * 16 + ((lane >> 3) & 1) * 8 + (lane & 7);
                    int c1 = s * 4 + (lane >> 4);
                    int c2 = c1 + 2;
                    ldsm4(&fb[np][0], sB + row * 256 + ((c1 & 8) << 4) + (((c1 ^ row) & 7) << 4));
                    ldsm4(&fb[np][4], sB + row * 256 + ((c2 & 8) << 4) + (((c2 ^ row) & 7) << 4));
                }
#pragma unroll
                for (int mt = 0; mt < 4; mt++)
#pragma unroll
                    for (int nt = 0; nt < 4; nt++) {
                        int np = nt >> 1, sub = nt & 1;
                        mmasp(acc[mt][nt], a[mt],
                              fb[np][sub], fb[np][2 + sub], fb[np][4 + sub], fb[np][6 + sub],
                              em[mt]);
                    }
            }
        }
        __syncthreads();
    }

    // Epilogue
    float* Dp = D + (size_t)(rowA0 + m_base) * OUT_F + blockIdx.x * BN + n_base;
#pragma unroll
    for (int mt = 0; mt < 4; mt++) {
#pragma unroll
        for (int nt = 0; nt < 4; nt++) {
            int r  = mt * 16 + (lane >> 2);
            int cc = nt * 8 + (lane & 3) * 2;
            *reinterpret_cast<float2*>(&Dp[(size_t)r * OUT_F + cc]) =
                make_float2(acc[mt][nt][0], acc[mt][nt][1]);
            *reinterpret_cast<float2*>(&Dp[(size_t)(r + 8) * OUT_F + cc]) =
                make_float2(acc[mt][nt][2], acc[mt][nt][3]);
        }
    }
}

// ---------------------------------------------------------------------------
extern "C" void kernel_launch(void* const* d_in, const int* in_sizes, int n_in,
                              void* d_out, int out_size) {
    const float* x    = (const float*)d_in[0];
    const float* bw   = (const float*)d_in[1];
    const float* sw   = (const float*)d_in[2];
    const float* sc   = (const float*)d_in[3];
    const float* grid = (const float*)d_in[4];
    float* out = (float*)d_out;

    build_A<<<(BATCH * IN_F) / 256, 256>>>(x, grid);
    build_B<<<(OUT_F * IN_F) / 256, 256>>>(bw, sw, sc);

    cudaFuncSetAttribute(gemm_sp, cudaFuncAttributeMaxDynamicSharedMemorySize, SMEM_TOT);
    dim3 grd(OUT_F / BN, BATCH / BM);   // (8, 32) = 256 CTAs, 2 per SM
    gemm_sp<<<grd, 256, SMEM_TOT>>>(out);
}